// round 13
// baseline (speedup 1.0000x reference)
#include <cuda_runtime.h>
#include <cuda_bf16.h>
#include <math.h>

// ---------------------------------------------------------------------------
// Problem constants
// ---------------------------------------------------------------------------
#define SEQ   2048
#define H     512
#define EDIM  512
#define G4H   2048            // 4*H
#define NTAGS 81
#define NEGV  (-10000.0f)

// ---------------------------------------------------------------------------
// Device scratch (static __device__ arrays: the sanctioned no-alloc workaround)
// ---------------------------------------------------------------------------
__device__ float g_U[2][SEQ * G4H];        // input projections + biases  (32 MB)
__device__ float g_hs[2][SEQ * H];         // per-step hidden states      (8 MB)
__device__ float g_hbuf[2][2][H];          // double-buffered recurrent h
__device__ float g_feats[SEQ * NTAGS];     // CRF emission scores
__device__ float g_fv2[SEQ * NTAGS];       // viterbi step_vars (for best_tag_score)
__device__ unsigned int g_cnt[2];          // barrier counters (per direction)
__device__ unsigned int g_flag[2];         // barrier release flags

// ---------------------------------------------------------------------------
// 0) reset barrier state each run (graph replays!)
// ---------------------------------------------------------------------------
__global__ void init_kernel() {
    if (threadIdx.x < 2) { g_cnt[threadIdx.x] = 0u; g_flag[threadIdx.x] = 0u; }
}

// ---------------------------------------------------------------------------
// 1) Input projection GEMM:
//    g_U[d][t][r] = sum_k emb[sent[t]][k] * Wih_d[r][k] + bih_d[r] + bhh_d[r]
//    M=2048 (t) x N=2048 (r) x K=512, 64x64 tiles, 4x4 register blocking.
// ---------------------------------------------------------------------------
__global__ void __launch_bounds__(256)
inproj_kernel(const int* __restrict__ sent, const float* __restrict__ emb,
              const float* __restrict__ Wf, const float* __restrict__ Wb,
              const float* __restrict__ bihf, const float* __restrict__ bhhf,
              const float* __restrict__ bihb, const float* __restrict__ bhhb)
{
    __shared__ float As[16][68];   // As[k][t]
    __shared__ float Bs[16][68];   // Bs[k][r]
    __shared__ int   srow[64];

    const int d  = blockIdx.z;
    const int r0 = blockIdx.x * 64;
    const int t0 = blockIdx.y * 64;
    const int tid = threadIdx.x;
    const float* W = d ? Wb : Wf;

    if (tid < 64) srow[tid] = sent[t0 + tid];
    __syncthreads();

    const int tx = tid & 15, ty = tid >> 4;
    float acc[4][4];
    #pragma unroll
    for (int i = 0; i < 4; i++)
        #pragma unroll
        for (int j = 0; j < 4; j++) acc[i][j] = 0.f;

    for (int k0 = 0; k0 < EDIM; k0 += 16) {
        #pragma unroll
        for (int m = 0; m < 4; m++) {
            int idx = tid + m * 256;
            int tt = idx >> 4, kk = idx & 15;
            As[kk][tt] = __ldg(&emb[(size_t)srow[tt] * EDIM + k0 + kk]);
            Bs[kk][tt] = __ldg(&W[(size_t)(r0 + tt) * EDIM + k0 + kk]);
        }
        __syncthreads();
        #pragma unroll
        for (int kk = 0; kk < 16; kk++) {
            float4 av = *(const float4*)&As[kk][ty * 4];
            float4 bv = *(const float4*)&Bs[kk][tx * 4];
            float aa[4] = {av.x, av.y, av.z, av.w};
            float bb[4] = {bv.x, bv.y, bv.z, bv.w};
            #pragma unroll
            for (int i = 0; i < 4; i++)
                #pragma unroll
                for (int j = 0; j < 4; j++)
                    acc[i][j] = fmaf(aa[i], bb[j], acc[i][j]);
        }
        __syncthreads();
    }

    float* outp = g_U[d];
    const float* bih = d ? bihb : bihf;
    const float* bhh = d ? bhhb : bhhf;
    #pragma unroll
    for (int i = 0; i < 4; i++) {
        int t = t0 + ty * 4 + i;
        #pragma unroll
        for (int j = 0; j < 4; j++) {
            int r = r0 + tx * 4 + j;
            outp[(size_t)t * G4H + r] = acc[i][j] + bih[r] + bhh[r];
        }
    }
}

// ---------------------------------------------------------------------------
// 2) Bidirectional LSTM recurrence.
//    128 persistent CTAs (64 per direction), 256 threads each.
//    Warp w of CTA cb owns h-element j = cb*8+w: its 4 gate rows'
//    Whh weights (4x512 fp32) live in registers (64 regs/thread).
//    Per step: read h (512 f32) from L2 (__ldcg), 64 FFMA/lane, butterfly
//    reduce, gate math, publish h_j, software barrier across the 64 CTAs.
// ---------------------------------------------------------------------------
__global__ void __launch_bounds__(256, 1)
lstm_kernel(const float* __restrict__ h0, const float* __restrict__ c0,
            const float* __restrict__ Whh_f, const float* __restrict__ Whh_b)
{
    const int d    = blockIdx.x >> 6;    // direction
    const int cb   = blockIdx.x & 63;    // CTA within direction
    const int w    = threadIdx.x >> 5;
    const int lane = threadIdx.x & 31;
    const int elem = cb * 8 + w;         // h element owned by this warp

    const float* Whh = d ? Whh_b : Whh_f;

    // Load recurrent weights into registers: wreg[gate q][k-chunk kk]
    float wreg[4][16];
    #pragma unroll
    for (int q = 0; q < 4; q++) {
        const float* wp = Whh + (size_t)(q * H + elem) * H + lane * 16;
        #pragma unroll
        for (int kk = 0; kk < 16; kk += 4) {
            float4 v = __ldg((const float4*)(wp + kk));
            wreg[q][kk] = v.x; wreg[q][kk + 1] = v.y;
            wreg[q][kk + 2] = v.z; wreg[q][kk + 3] = v.w;
        }
    }
    float cst = c0[d * H + elem];

    const float* Ud    = g_U[d];
    float*       hsarr = g_hs[d];

    __shared__ unsigned int scnt;
    if (threadIdx.x == 0) scnt = 0u;
    __syncthreads();

    for (int step = 0; step < SEQ; ++step) {
        const int t = d ? (SEQ - 1 - step) : step;

        // input-projection terms (same address across warp -> broadcast)
        const float* up = Ud + (size_t)t * G4H + elem;
        float u0 = __ldcg(up);
        float u1 = __ldcg(up + H);
        float u2 = __ldcg(up + 2 * H);
        float u3 = __ldcg(up + 3 * H);

        // previous h (must bypass L1: written by other SMs, buffers reused)
        const float* hsrc = (step == 0) ? (h0 + d * H) : g_hbuf[d][step & 1];
        float hv[16];
        const float4* hp = ((const float4*)hsrc) + lane * 4;
        #pragma unroll
        for (int m = 0; m < 4; m++) {
            float4 v = __ldcg(hp + m);
            hv[4 * m] = v.x; hv[4 * m + 1] = v.y; hv[4 * m + 2] = v.z; hv[4 * m + 3] = v.w;
        }

        float s0 = 0.f, s1 = 0.f, s2 = 0.f, s3 = 0.f;
        #pragma unroll
        for (int kk = 0; kk < 16; kk++) {
            float hk = hv[kk];
            s0 = fmaf(wreg[0][kk], hk, s0);
            s1 = fmaf(wreg[1][kk], hk, s1);
            s2 = fmaf(wreg[2][kk], hk, s2);
            s3 = fmaf(wreg[3][kk], hk, s3);
        }
        #pragma unroll
        for (int off = 16; off; off >>= 1) {
            s0 += __shfl_xor_sync(0xffffffffu, s0, off);
            s1 += __shfl_xor_sync(0xffffffffu, s1, off);
            s2 += __shfl_xor_sync(0xffffffffu, s2, off);
            s3 += __shfl_xor_sync(0xffffffffu, s3, off);
        }

        // gate math (all lanes identical; keeps c replicated, no divergence)
        float gi = s0 + u0, gf = s1 + u1, gg = s2 + u2, go = s3 + u3;
        float ii = 1.f / (1.f + expf(-gi));
        float ff = 1.f / (1.f + expf(-gf));
        float oo = 1.f / (1.f + expf(-go));
        float gt = tanhf(gg);
        cst = ff * cst + ii * gt;
        float hn = oo * tanhf(cst);

        if (lane == 0) {
            g_hbuf[d][(step + 1) & 1][elem] = hn;
            hsarr[(size_t)t * H + elem]     = hn;

            // ---- software barrier across the 64 CTAs of this direction ----
            __threadfence();                              // publish hn to L2
            unsigned p = atomicAdd(&scnt, 1u);            // intra-CTA (8 warps)
            if (p == 7u) {
                atomicExch(&scnt, 0u);
                unsigned prev = atomicAdd(&g_cnt[d], 1u); // inter-CTA (64 CTAs)
                if (prev == 63u) {
                    atomicExch(&g_cnt[d], 0u);
                    __threadfence();
                    atomicExch(&g_flag[d], (unsigned)(step + 1));
                } else {
                    while (*(volatile unsigned int*)&g_flag[d] < (unsigned)(step + 1)) {}
                }
            } else {
                while (*(volatile unsigned int*)&g_flag[d] < (unsigned)(step + 1)) {}
            }
        }
        __syncwarp();
    }
}

// ---------------------------------------------------------------------------
// 3) feats[t][n] = concat(hf[t], hb[t]) . Wt[n] + bt[n]
// ---------------------------------------------------------------------------
__global__ void __launch_bounds__(128)
feats_kernel(const float* __restrict__ Wt, const float* __restrict__ bt)
{
    __shared__ float hcat[2 * H];
    const int t = blockIdx.x;
    const int tid = threadIdx.x;
    for (int k = tid; k < H; k += 128) {
        hcat[k]     = g_hs[0][(size_t)t * H + k];
        hcat[H + k] = g_hs[1][(size_t)t * H + k];
    }
    __syncthreads();
    if (tid < NTAGS) {
        float acc = bt[tid];
        const float* wr = Wt + (size_t)tid * (2 * H);
        #pragma unroll 8
        for (int k = 0; k < 2 * H; k += 4) {
            float4 wv = __ldg((const float4*)(wr + k));
            acc = fmaf(hcat[k], wv.x, acc);
            acc = fmaf(hcat[k + 1], wv.y, acc);
            acc = fmaf(hcat[k + 2], wv.z, acc);
            acc = fmaf(hcat[k + 3], wv.w, acc);
        }
        g_feats[t * NTAGS + tid] = acc;
    }
}

// ---------------------------------------------------------------------------
// 4) Viterbi: single CTA, 672 threads (81 tags x 8 lanes, padded to warps).
//    Backpointers live in SMEM (166 KB) so the backtrack chain runs at LDS
//    latency. Tie-break matches jnp.argmax (first/lowest index).
//    Output layout (float32): [path_score(1) | best_path(2048) | best_tag_score(2048)]
// ---------------------------------------------------------------------------
#define VIT_SMEM ((NTAGS*NTAGS + 2*NTAGS) * 4 + SEQ * NTAGS)

__global__ void __launch_bounds__(672)
viterbi_kernel(const float* __restrict__ trans, float* __restrict__ out)
{
    extern __shared__ unsigned char smraw[];
    float* strans = (float*)smraw;                       // 81*81
    float* fvb    = strans + NTAGS * NTAGS;              // 2*81 (double buffer)
    unsigned char* bp = (unsigned char*)(fvb + 2 * NTAGS); // 2048*81
    __shared__ int sbest;

    const int tid = threadIdx.x;
    for (int i = tid; i < NTAGS * NTAGS; i += 672) strans[i] = trans[i];
    if (tid < NTAGS) fvb[tid] = (tid == 79) ? 0.0f : NEGV;   // START=79
    __syncthreads();

    const int i  = tid >> 3;      // target tag
    const int li = tid & 7;       // lane within tag group

    // cache this thread's slice of the transition row in registers
    float trreg[11];
    #pragma unroll
    for (int m = 0; m < 11; m++) {
        int j = li + 8 * m;
        trreg[m] = (i < NTAGS && j < NTAGS) ? strans[i * NTAGS + j] : 0.f;
    }

    for (int t = 0; t < SEQ; t++) {
        const float* fvc = fvb + (t & 1) * NTAGS;
        float*       fvn = fvb + ((t + 1) & 1) * NTAGS;

        float ft = (i < NTAGS && li == 0) ? __ldg(&g_feats[t * NTAGS + i]) : 0.f;

        float best = -3.4e38f; int bj = 0;
        if (i < NTAGS) {
            #pragma unroll
            for (int m = 0; m < 11; m++) {
                int j = li + 8 * m;
                if (j < NTAGS) {
                    float v = fvc[j] + trreg[m];
                    if (v > best) { best = v; bj = j; }
                }
            }
        }
        #pragma unroll
        for (int off = 4; off; off >>= 1) {
            float v2 = __shfl_xor_sync(0xffffffffu, best, off);
            int   j2 = __shfl_xor_sync(0xffffffffu, bj, off);
            if (v2 > best || (v2 == best && j2 < bj)) { best = v2; bj = j2; }
        }
        if (i < NTAGS && li == 0) {
            float nv = best + ft;
            fvn[i] = nv;
            bp[t * NTAGS + i] = (unsigned char)bj;
            g_fv2[t * NTAGS + i] = nv;
        }
        __syncthreads();
    }

    if (tid == 0) {
        const float* fvl  = fvb;                     // (SEQ&1)==0 buffer
        const float* trow = strans + 80 * NTAGS;     // transitions[STOP=80]
        float bv = -3.4e38f; int bi = 0;
        for (int j = 0; j < NTAGS; j++) {
            float v = fvl[j] + trow[j];
            if (v > bv) { bv = v; bi = j; }
        }
        out[0] = bv;                                 // path_score
        sbest  = bi;
        int cur = bi;
        out[1 + SEQ - 1] = (float)cur;               // best_path[T-1]
        for (int t = SEQ - 1; t >= 1; --t) {
            cur = bp[t * NTAGS + cur];
            out[t] = (float)cur;                     // best_path[t-1]
        }
    }
    __syncthreads();
    const int b = sbest;
    for (int k = tid; k < SEQ; k += 672)             // best_tag_score[k] = fv2[T-1-k][best]
        out[1 + SEQ + k] = g_fv2[(SEQ - 1 - k) * NTAGS + b];
}

// ---------------------------------------------------------------------------
// Launch
// ---------------------------------------------------------------------------
extern "C" void kernel_launch(void* const* d_in, const int* in_sizes, int n_in,
                              void* d_out, int out_size)
{
    (void)in_sizes; (void)n_in; (void)out_size;
    const int*   sent  = (const int*)  d_in[0];
    const float* h0    = (const float*)d_in[1];
    const float* c0    = (const float*)d_in[2];
    const float* emb   = (const float*)d_in[3];
    const float* Wih_f = (const float*)d_in[4];
    const float* Whh_f = (const float*)d_in[5];
    const float* bih_f = (const float*)d_in[6];
    const float* bhh_f = (const float*)d_in[7];
    const float* Wih_b = (const float*)d_in[8];
    const float* Whh_b = (const float*)d_in[9];
    const float* bih_b = (const float*)d_in[10];
    const float* bhh_b = (const float*)d_in[11];
    const float* Wt    = (const float*)d_in[12];
    const float* bt    = (const float*)d_in[13];
    const float* trans = (const float*)d_in[14];
    float* out = (float*)d_out;

    init_kernel<<<1, 32>>>();

    dim3 g(G4H / 64, SEQ / 64, 2);
    inproj_kernel<<<g, 256>>>(sent, emb, Wih_f, Wih_b, bih_f, bhh_f, bih_b, bhh_b);

    lstm_kernel<<<128, 256>>>(h0, c0, Whh_f, Whh_b);

    feats_kernel<<<SEQ, 128>>>(Wt, bt);

    cudaFuncSetAttribute(viterbi_kernel,
                         cudaFuncAttributeMaxDynamicSharedMemorySize, VIT_SMEM);
    viterbi_kernel<<<1, 672, VIT_SMEM>>>(trans, out);
}

// round 14
// speedup vs baseline: 1.0109x; 1.0109x over previous
#include <cuda_runtime.h>
#include <cuda_bf16.h>
#include <math.h>

// ---------------------------------------------------------------------------
// Problem constants
// ---------------------------------------------------------------------------
#define SEQ   2048
#define H     512
#define EDIM  512
#define G4H   2048            // 4*H
#define NTAGS 81
#define NEGV  (-10000.0f)

// ---------------------------------------------------------------------------
// Device scratch (static __device__ arrays: the sanctioned no-alloc workaround)
// ---------------------------------------------------------------------------
__device__ float g_U[2][SEQ * G4H];        // input projections + biases  (32 MB)
__device__ float g_hs[2][SEQ * H];         // per-step hidden states      (8 MB)
__device__ float g_hbuf[2][2][H];          // double-buffered recurrent h
__device__ float g_feats[SEQ * NTAGS];     // CRF emission scores
__device__ float g_fv2[SEQ * NTAGS];       // viterbi step_vars (for best_tag_score)
__device__ unsigned int g_cnt[2];          // barrier counters (per direction)
__device__ unsigned int g_flag[2];         // barrier release flags

// ---------------------------------------------------------------------------
// 0) reset barrier state each run (graph replays!)
// ---------------------------------------------------------------------------
__global__ void init_kernel() {
    if (threadIdx.x < 2) { g_cnt[threadIdx.x] = 0u; g_flag[threadIdx.x] = 0u; }
}

// ---------------------------------------------------------------------------
// 1) Input projection GEMM:
//    g_U[d][t][r] = sum_k emb[sent[t]][k] * Wih_d[r][k] + bih_d[r] + bhh_d[r]
//    M=2048 (t) x N=2048 (r) x K=512, 64x64 tiles, 4x4 register blocking.
// ---------------------------------------------------------------------------
__global__ void __launch_bounds__(256)
inproj_kernel(const int* __restrict__ sent, const float* __restrict__ emb,
              const float* __restrict__ Wf, const float* __restrict__ Wb,
              const float* __restrict__ bihf, const float* __restrict__ bhhf,
              const float* __restrict__ bihb, const float* __restrict__ bhhb)
{
    __shared__ float As[16][68];   // As[k][t]
    __shared__ float Bs[16][68];   // Bs[k][r]
    __shared__ int   srow[64];

    const int d  = blockIdx.z;
    const int r0 = blockIdx.x * 64;
    const int t0 = blockIdx.y * 64;
    const int tid = threadIdx.x;
    const float* W = d ? Wb : Wf;

    if (tid < 64) srow[tid] = sent[t0 + tid];
    __syncthreads();

    const int tx = tid & 15, ty = tid >> 4;
    float acc[4][4];
    #pragma unroll
    for (int i = 0; i < 4; i++)
        #pragma unroll
        for (int j = 0; j < 4; j++) acc[i][j] = 0.f;

    for (int k0 = 0; k0 < EDIM; k0 += 16) {
        #pragma unroll
        for (int m = 0; m < 4; m++) {
            int idx = tid + m * 256;
            int tt = idx >> 4, kk = idx & 15;
            As[kk][tt] = __ldg(&emb[(size_t)srow[tt] * EDIM + k0 + kk]);
            Bs[kk][tt] = __ldg(&W[(size_t)(r0 + tt) * EDIM + k0 + kk]);
        }
        __syncthreads();
        #pragma unroll
        for (int kk = 0; kk < 16; kk++) {
            float4 av = *(const float4*)&As[kk][ty * 4];
            float4 bv = *(const float4*)&Bs[kk][tx * 4];
            float aa[4] = {av.x, av.y, av.z, av.w};
            float bb[4] = {bv.x, bv.y, bv.z, bv.w};
            #pragma unroll
            for (int i = 0; i < 4; i++)
                #pragma unroll
                for (int j = 0; j < 4; j++)
                    acc[i][j] = fmaf(aa[i], bb[j], acc[i][j]);
        }
        __syncthreads();
    }

    float* outp = g_U[d];
    const float* bih = d ? bihb : bihf;
    const float* bhh = d ? bhhb : bhhf;
    #pragma unroll
    for (int i = 0; i < 4; i++) {
        int t = t0 + ty * 4 + i;
        #pragma unroll
        for (int j = 0; j < 4; j++) {
            int r = r0 + tx * 4 + j;
            outp[(size_t)t * G4H + r] = acc[i][j] + bih[r] + bhh[r];
        }
    }
}

// ---------------------------------------------------------------------------
// 2) Bidirectional LSTM recurrence.
//    128 persistent CTAs (64 per direction), 256 threads each.
//    Warp w of CTA cb owns h-element j = cb*8+w: its 4 gate rows'
//    Whh weights (4x512 fp32) live in registers (64 regs/thread).
//    Per step: read h (512 f32) from L2 (__ldcg), 64 FFMA/lane, butterfly
//    reduce, gate math, publish h_j, software barrier across the 64 CTAs.
// ---------------------------------------------------------------------------
__global__ void __launch_bounds__(256, 1)
lstm_kernel(const float* __restrict__ h0, const float* __restrict__ c0,
            const float* __restrict__ Whh_f, const float* __restrict__ Whh_b)
{
    const int d    = blockIdx.x >> 6;    // direction
    const int cb   = blockIdx.x & 63;    // CTA within direction
    const int w    = threadIdx.x >> 5;
    const int lane = threadIdx.x & 31;
    const int elem = cb * 8 + w;         // h element owned by this warp

    const float* Whh = d ? Whh_b : Whh_f;

    // Load recurrent weights into registers: wreg[gate q][k-chunk kk]
    float wreg[4][16];
    #pragma unroll
    for (int q = 0; q < 4; q++) {
        const float* wp = Whh + (size_t)(q * H + elem) * H + lane * 16;
        #pragma unroll
        for (int kk = 0; kk < 16; kk += 4) {
            float4 v = __ldg((const float4*)(wp + kk));
            wreg[q][kk] = v.x; wreg[q][kk + 1] = v.y;
            wreg[q][kk + 2] = v.z; wreg[q][kk + 3] = v.w;
        }
    }
    float cst = c0[d * H + elem];

    const float* Ud    = g_U[d];
    float*       hsarr = g_hs[d];

    __shared__ unsigned int scnt;
    if (threadIdx.x == 0) scnt = 0u;
    __syncthreads();

    for (int step = 0; step < SEQ; ++step) {
        const int t = d ? (SEQ - 1 - step) : step;

        // input-projection terms (same address across warp -> broadcast)
        const float* up = Ud + (size_t)t * G4H + elem;
        float u0 = __ldcg(up);
        float u1 = __ldcg(up + H);
        float u2 = __ldcg(up + 2 * H);
        float u3 = __ldcg(up + 3 * H);

        // previous h (must bypass L1: written by other SMs, buffers reused)
        const float* hsrc = (step == 0) ? (h0 + d * H) : g_hbuf[d][step & 1];
        float hv[16];
        const float4* hp = ((const float4*)hsrc) + lane * 4;
        #pragma unroll
        for (int m = 0; m < 4; m++) {
            float4 v = __ldcg(hp + m);
            hv[4 * m] = v.x; hv[4 * m + 1] = v.y; hv[4 * m + 2] = v.z; hv[4 * m + 3] = v.w;
        }

        float s0 = 0.f, s1 = 0.f, s2 = 0.f, s3 = 0.f;
        #pragma unroll
        for (int kk = 0; kk < 16; kk++) {
            float hk = hv[kk];
            s0 = fmaf(wreg[0][kk], hk, s0);
            s1 = fmaf(wreg[1][kk], hk, s1);
            s2 = fmaf(wreg[2][kk], hk, s2);
            s3 = fmaf(wreg[3][kk], hk, s3);
        }
        #pragma unroll
        for (int off = 16; off; off >>= 1) {
            s0 += __shfl_xor_sync(0xffffffffu, s0, off);
            s1 += __shfl_xor_sync(0xffffffffu, s1, off);
            s2 += __shfl_xor_sync(0xffffffffu, s2, off);
            s3 += __shfl_xor_sync(0xffffffffu, s3, off);
        }

        // gate math (all lanes identical; keeps c replicated, no divergence)
        float gi = s0 + u0, gf = s1 + u1, gg = s2 + u2, go = s3 + u3;
        float ii = 1.f / (1.f + expf(-gi));
        float ff = 1.f / (1.f + expf(-gf));
        float oo = 1.f / (1.f + expf(-go));
        float gt = tanhf(gg);
        cst = ff * cst + ii * gt;
        float hn = oo * tanhf(cst);

        if (lane == 0) {
            g_hbuf[d][(step + 1) & 1][elem] = hn;
            hsarr[(size_t)t * H + elem]     = hn;

            // ---- software barrier across the 64 CTAs of this direction ----
            __threadfence();                              // publish hn to L2
            unsigned p = atomicAdd(&scnt, 1u);            // intra-CTA (8 warps)
            if (p == 7u) {
                atomicExch(&scnt, 0u);
                unsigned prev = atomicAdd(&g_cnt[d], 1u); // inter-CTA (64 CTAs)
                if (prev == 63u) {
                    atomicExch(&g_cnt[d], 0u);
                    __threadfence();
                    atomicExch(&g_flag[d], (unsigned)(step + 1));
                } else {
                    while (*(volatile unsigned int*)&g_flag[d] < (unsigned)(step + 1)) {}
                }
            } else {
                while (*(volatile unsigned int*)&g_flag[d] < (unsigned)(step + 1)) {}
            }
        }
        __syncwarp();
    }
}

// ---------------------------------------------------------------------------
// 3) feats[t][n] = concat(hf[t], hb[t]) . Wt[n] + bt[n]
// ---------------------------------------------------------------------------
__global__ void __launch_bounds__(128)
feats_kernel(const float* __restrict__ Wt, const float* __restrict__ bt)
{
    __shared__ float hcat[2 * H];
    const int t = blockIdx.x;
    const int tid = threadIdx.x;
    for (int k = tid; k < H; k += 128) {
        hcat[k]     = g_hs[0][(size_t)t * H + k];
        hcat[H + k] = g_hs[1][(size_t)t * H + k];
    }
    __syncthreads();
    if (tid < NTAGS) {
        float acc = bt[tid];
        const float* wr = Wt + (size_t)tid * (2 * H);
        #pragma unroll 8
        for (int k = 0; k < 2 * H; k += 4) {
            float4 wv = __ldg((const float4*)(wr + k));
            acc = fmaf(hcat[k], wv.x, acc);
            acc = fmaf(hcat[k + 1], wv.y, acc);
            acc = fmaf(hcat[k + 2], wv.z, acc);
            acc = fmaf(hcat[k + 3], wv.w, acc);
        }
        g_feats[t * NTAGS + tid] = acc;
    }
}

// ---------------------------------------------------------------------------
// 4) Viterbi: single CTA, 672 threads (81 tags x 8 lanes, padded to warps).
//    Backpointers live in SMEM (166 KB) so the backtrack chain runs at LDS
//    latency. Tie-break matches jnp.argmax (first/lowest index).
//    Output layout (float32): [path_score(1) | best_path(2048) | best_tag_score(2048)]
// ---------------------------------------------------------------------------
#define VIT_SMEM ((NTAGS*NTAGS + 2*NTAGS) * 4 + SEQ * NTAGS)

__global__ void __launch_bounds__(672)
viterbi_kernel(const float* __restrict__ trans, float* __restrict__ out)
{
    extern __shared__ unsigned char smraw[];
    float* strans = (float*)smraw;                       // 81*81
    float* fvb    = strans + NTAGS * NTAGS;              // 2*81 (double buffer)
    unsigned char* bp = (unsigned char*)(fvb + 2 * NTAGS); // 2048*81
    __shared__ int sbest;

    const int tid = threadIdx.x;
    for (int i = tid; i < NTAGS * NTAGS; i += 672) strans[i] = trans[i];
    if (tid < NTAGS) fvb[tid] = (tid == 79) ? 0.0f : NEGV;   // START=79
    __syncthreads();

    const int i  = tid >> 3;      // target tag
    const int li = tid & 7;       // lane within tag group

    // cache this thread's slice of the transition row in registers
    float trreg[11];
    #pragma unroll
    for (int m = 0; m < 11; m++) {
        int j = li + 8 * m;
        trreg[m] = (i < NTAGS && j < NTAGS) ? strans[i * NTAGS + j] : 0.f;
    }

    for (int t = 0; t < SEQ; t++) {
        const float* fvc = fvb + (t & 1) * NTAGS;
        float*       fvn = fvb + ((t + 1) & 1) * NTAGS;

        float ft = (i < NTAGS && li == 0) ? __ldg(&g_feats[t * NTAGS + i]) : 0.f;

        float best = -3.4e38f; int bj = 0;
        if (i < NTAGS) {
            #pragma unroll
            for (int m = 0; m < 11; m++) {
                int j = li + 8 * m;
                if (j < NTAGS) {
                    float v = fvc[j] + trreg[m];
                    if (v > best) { best = v; bj = j; }
                }
            }
        }
        #pragma unroll
        for (int off = 4; off; off >>= 1) {
            float v2 = __shfl_xor_sync(0xffffffffu, best, off);
            int   j2 = __shfl_xor_sync(0xffffffffu, bj, off);
            if (v2 > best || (v2 == best && j2 < bj)) { best = v2; bj = j2; }
        }
        if (i < NTAGS && li == 0) {
            float nv = best + ft;
            fvn[i] = nv;
            bp[t * NTAGS + i] = (unsigned char)bj;
            g_fv2[t * NTAGS + i] = nv;
        }
        __syncthreads();
    }

    if (tid == 0) {
        const float* fvl  = fvb;                     // (SEQ&1)==0 buffer
        const float* trow = strans + 80 * NTAGS;     // transitions[STOP=80]
        float bv = -3.4e38f; int bi = 0;
        for (int j = 0; j < NTAGS; j++) {
            float v = fvl[j] + trow[j];
            if (v > bv) { bv = v; bi = j; }
        }
        out[0] = bv;                                 // path_score
        sbest  = bi;
        int cur = bi;
        out[1 + SEQ - 1] = (float)cur;               // best_path[T-1]
        for (int t = SEQ - 1; t >= 1; --t) {
            cur = bp[t * NTAGS + cur];
            out[t] = (float)cur;                     // best_path[t-1]
        }
    }
    __syncthreads();
    const int b = sbest;
    for (int k = tid; k < SEQ; k += 672)             // best_tag_score[k] = fv2[T-1-k][best]
        out[1 + SEQ + k] = g_fv2[(SEQ - 1 - k) * NTAGS + b];
}

// ---------------------------------------------------------------------------
// Launch
// ---------------------------------------------------------------------------
extern "C" void kernel_launch(void* const* d_in, const int* in_sizes, int n_in,
                              void* d_out, int out_size)
{
    (void)in_sizes; (void)n_in; (void)out_size;
    const int*   sent  = (const int*)  d_in[0];
    const float* h0    = (const float*)d_in[1];
    const float* c0    = (const float*)d_in[2];
    const float* emb   = (const float*)d_in[3];
    const float* Wih_f = (const float*)d_in[4];
    const float* Whh_f = (const float*)d_in[5];
    const float* bih_f = (const float*)d_in[6];
    const float* bhh_f = (const float*)d_in[7];
    const float* Wih_b = (const float*)d_in[8];
    const float* Whh_b = (const float*)d_in[9];
    const float* bih_b = (const float*)d_in[10];
    const float* bhh_b = (const float*)d_in[11];
    const float* Wt    = (const float*)d_in[12];
    const float* bt    = (const float*)d_in[13];
    const float* trans = (const float*)d_in[14];
    float* out = (float*)d_out;

    init_kernel<<<1, 32>>>();

    dim3 g(G4H / 64, SEQ / 64, 2);
    inproj_kernel<<<g, 256>>>(sent, emb, Wih_f, Wih_b, bih_f, bhh_f, bih_b, bhh_b);

    lstm_kernel<<<128, 256>>>(h0, c0, Whh_f, Whh_b);

    feats_kernel<<<SEQ, 128>>>(Wt, bt);

    cudaFuncSetAttribute(viterbi_kernel,
                         cudaFuncAttributeMaxDynamicSharedMemorySize, VIT_SMEM);
    viterbi_kernel<<<1, 672, VIT_SMEM>>>(trans, out);
}

// round 15
// speedup vs baseline: 1.1605x; 1.1480x over previous
#include <cuda_runtime.h>
#include <cuda_bf16.h>
#include <math.h>

// ---------------------------------------------------------------------------
// Problem constants
// ---------------------------------------------------------------------------
#define SEQ   2048
#define H     512
#define EDIM  512
#define G4H   2048            // 4*H
#define NTAGS 81
#define NEGV  (-10000.0f)

// ---------------------------------------------------------------------------
// Device scratch (static __device__ arrays: the sanctioned no-alloc workaround)
// ---------------------------------------------------------------------------
__device__ float g_U[2][SEQ * G4H];        // input projections + biases  (32 MB)
__device__ float g_hs[2][SEQ * H];         // per-step hidden states      (8 MB)
__device__ float g_hbuf[2][2][H];          // double-buffered recurrent h
__device__ float g_feats[SEQ * NTAGS];     // CRF emission scores
__device__ float g_fv2[SEQ * NTAGS];       // viterbi step_vars (for best_tag_score)
__device__ unsigned int g_cnt[2];          // barrier counters (per direction)
__device__ unsigned int g_flag[2];         // barrier release flags

// ---------------------------------------------------------------------------
// 0) reset barrier state each run (graph replays!)
// ---------------------------------------------------------------------------
__global__ void init_kernel() {
    if (threadIdx.x < 2) { g_cnt[threadIdx.x] = 0u; g_flag[threadIdx.x] = 0u; }
}

// ---------------------------------------------------------------------------
// 1) Input projection GEMM:
//    g_U[d][t][r] = sum_k emb[sent[t]][k] * Wih_d[r][k] + bih_d[r] + bhh_d[r]
//    M=2048 (t) x N=2048 (r) x K=512, 64x64 tiles, 4x4 register blocking.
// ---------------------------------------------------------------------------
__global__ void __launch_bounds__(256)
inproj_kernel(const int* __restrict__ sent, const float* __restrict__ emb,
              const float* __restrict__ Wf, const float* __restrict__ Wb,
              const float* __restrict__ bihf, const float* __restrict__ bhhf,
              const float* __restrict__ bihb, const float* __restrict__ bhhb)
{
    __shared__ float As[16][68];   // As[k][t]
    __shared__ float Bs[16][68];   // Bs[k][r]
    __shared__ int   srow[64];

    const int d  = blockIdx.z;
    const int r0 = blockIdx.x * 64;
    const int t0 = blockIdx.y * 64;
    const int tid = threadIdx.x;
    const float* W = d ? Wb : Wf;

    if (tid < 64) srow[tid] = sent[t0 + tid];
    __syncthreads();

    const int tx = tid & 15, ty = tid >> 4;
    float acc[4][4];
    #pragma unroll
    for (int i = 0; i < 4; i++)
        #pragma unroll
        for (int j = 0; j < 4; j++) acc[i][j] = 0.f;

    for (int k0 = 0; k0 < EDIM; k0 += 16) {
        #pragma unroll
        for (int m = 0; m < 4; m++) {
            int idx = tid + m * 256;
            int tt = idx >> 4, kk = idx & 15;
            As[kk][tt] = __ldg(&emb[(size_t)srow[tt] * EDIM + k0 + kk]);
            Bs[kk][tt] = __ldg(&W[(size_t)(r0 + tt) * EDIM + k0 + kk]);
        }
        __syncthreads();
        #pragma unroll
        for (int kk = 0; kk < 16; kk++) {
            float4 av = *(const float4*)&As[kk][ty * 4];
            float4 bv = *(const float4*)&Bs[kk][tx * 4];
            float aa[4] = {av.x, av.y, av.z, av.w};
            float bb[4] = {bv.x, bv.y, bv.z, bv.w};
            #pragma unroll
            for (int i = 0; i < 4; i++)
                #pragma unroll
                for (int j = 0; j < 4; j++)
                    acc[i][j] = fmaf(aa[i], bb[j], acc[i][j]);
        }
        __syncthreads();
    }

    float* outp = g_U[d];
    const float* bih = d ? bihb : bihf;
    const float* bhh = d ? bhhb : bhhf;
    #pragma unroll
    for (int i = 0; i < 4; i++) {
        int t = t0 + ty * 4 + i;
        #pragma unroll
        for (int j = 0; j < 4; j++) {
            int r = r0 + tx * 4 + j;
            outp[(size_t)t * G4H + r] = acc[i][j] + bih[r] + bhh[r];
        }
    }
}

// ---------------------------------------------------------------------------
// 2) Bidirectional LSTM recurrence.
//    128 persistent CTAs (64 per direction), 256 threads each.
//    Warp w of CTA cb owns h-element j = cb*8+w: its 4 gate rows'
//    Whh weights (4x512 fp32) live in registers (64 regs/thread).
//    Per step: read h (512 f32) from L2 (__ldcg), 64 FFMA/lane, butterfly
//    reduce, gate math, publish h_j, software barrier across the 64 CTAs.
// ---------------------------------------------------------------------------
__global__ void __launch_bounds__(256, 1)
lstm_kernel(const float* __restrict__ h0, const float* __restrict__ c0,
            const float* __restrict__ Whh_f, const float* __restrict__ Whh_b)
{
    const int d    = blockIdx.x >> 6;    // direction
    const int cb   = blockIdx.x & 63;    // CTA within direction
    const int w    = threadIdx.x >> 5;
    const int lane = threadIdx.x & 31;
    const int elem = cb * 8 + w;         // h element owned by this warp

    const float* Whh = d ? Whh_b : Whh_f;

    // Load recurrent weights into registers: wreg[gate q][k-chunk kk]
    float wreg[4][16];
    #pragma unroll
    for (int q = 0; q < 4; q++) {
        const float* wp = Whh + (size_t)(q * H + elem) * H + lane * 16;
        #pragma unroll
        for (int kk = 0; kk < 16; kk += 4) {
            float4 v = __ldg((const float4*)(wp + kk));
            wreg[q][kk] = v.x; wreg[q][kk + 1] = v.y;
            wreg[q][kk + 2] = v.z; wreg[q][kk + 3] = v.w;
        }
    }
    float cst = c0[d * H + elem];

    const float* Ud    = g_U[d];
    float*       hsarr = g_hs[d];

    __shared__ unsigned int scnt;
    if (threadIdx.x == 0) scnt = 0u;
    __syncthreads();

    for (int step = 0; step < SEQ; ++step) {
        const int t = d ? (SEQ - 1 - step) : step;

        // input-projection terms (same address across warp -> broadcast)
        const float* up = Ud + (size_t)t * G4H + elem;
        float u0 = __ldcg(up);
        float u1 = __ldcg(up + H);
        float u2 = __ldcg(up + 2 * H);
        float u3 = __ldcg(up + 3 * H);

        // previous h (must bypass L1: written by other SMs, buffers reused)
        const float* hsrc = (step == 0) ? (h0 + d * H) : g_hbuf[d][step & 1];
        float hv[16];
        const float4* hp = ((const float4*)hsrc) + lane * 4;
        #pragma unroll
        for (int m = 0; m < 4; m++) {
            float4 v = __ldcg(hp + m);
            hv[4 * m] = v.x; hv[4 * m + 1] = v.y; hv[4 * m + 2] = v.z; hv[4 * m + 3] = v.w;
        }

        float s0 = 0.f, s1 = 0.f, s2 = 0.f, s3 = 0.f;
        #pragma unroll
        for (int kk = 0; kk < 16; kk++) {
            float hk = hv[kk];
            s0 = fmaf(wreg[0][kk], hk, s0);
            s1 = fmaf(wreg[1][kk], hk, s1);
            s2 = fmaf(wreg[2][kk], hk, s2);
            s3 = fmaf(wreg[3][kk], hk, s3);
        }
        #pragma unroll
        for (int off = 16; off; off >>= 1) {
            s0 += __shfl_xor_sync(0xffffffffu, s0, off);
            s1 += __shfl_xor_sync(0xffffffffu, s1, off);
            s2 += __shfl_xor_sync(0xffffffffu, s2, off);
            s3 += __shfl_xor_sync(0xffffffffu, s3, off);
        }

        // gate math (all lanes identical; keeps c replicated, no divergence)
        float gi = s0 + u0, gf = s1 + u1, gg = s2 + u2, go = s3 + u3;
        float ii = 1.f / (1.f + expf(-gi));
        float ff = 1.f / (1.f + expf(-gf));
        float oo = 1.f / (1.f + expf(-go));
        float gt = tanhf(gg);
        cst = ff * cst + ii * gt;
        float hn = oo * tanhf(cst);

        if (lane == 0) {
            g_hbuf[d][(step + 1) & 1][elem] = hn;
            hsarr[(size_t)t * H + elem]     = hn;

            // ---- software barrier across the 64 CTAs of this direction ----
            __threadfence();                              // publish hn to L2
            unsigned p = atomicAdd(&scnt, 1u);            // intra-CTA (8 warps)
            if (p == 7u) {
                atomicExch(&scnt, 0u);
                unsigned prev = atomicAdd(&g_cnt[d], 1u); // inter-CTA (64 CTAs)
                if (prev == 63u) {
                    atomicExch(&g_cnt[d], 0u);
                    __threadfence();
                    atomicExch(&g_flag[d], (unsigned)(step + 1));
                } else {
                    while (*(volatile unsigned int*)&g_flag[d] < (unsigned)(step + 1)) {}
                }
            } else {
                while (*(volatile unsigned int*)&g_flag[d] < (unsigned)(step + 1)) {}
            }
        }
        __syncwarp();
    }
}

// ---------------------------------------------------------------------------
// 3) feats[t][n] = concat(hf[t], hb[t]) . Wt[n] + bt[n]
// ---------------------------------------------------------------------------
__global__ void __launch_bounds__(128)
feats_kernel(const float* __restrict__ Wt, const float* __restrict__ bt)
{
    __shared__ float hcat[2 * H];
    const int t = blockIdx.x;
    const int tid = threadIdx.x;
    for (int k = tid; k < H; k += 128) {
        hcat[k]     = g_hs[0][(size_t)t * H + k];
        hcat[H + k] = g_hs[1][(size_t)t * H + k];
    }
    __syncthreads();
    if (tid < NTAGS) {
        float acc = bt[tid];
        const float* wr = Wt + (size_t)tid * (2 * H);
        #pragma unroll 8
        for (int k = 0; k < 2 * H; k += 4) {
            float4 wv = __ldg((const float4*)(wr + k));
            acc = fmaf(hcat[k], wv.x, acc);
            acc = fmaf(hcat[k + 1], wv.y, acc);
            acc = fmaf(hcat[k + 2], wv.z, acc);
            acc = fmaf(hcat[k + 3], wv.w, acc);
        }
        g_feats[t * NTAGS + tid] = acc;
    }
}

// ---------------------------------------------------------------------------
// 4) Viterbi: single CTA, 672 threads (81 tags x 8 lanes, padded to warps).
//    Backpointers live in SMEM (166 KB) so the backtrack chain runs at LDS
//    latency. Tie-break matches jnp.argmax (first/lowest index).
//    Output layout (float32): [path_score(1) | best_path(2048) | best_tag_score(2048)]
// ---------------------------------------------------------------------------
#define VIT_SMEM ((NTAGS*NTAGS + 2*NTAGS) * 4 + SEQ * NTAGS)

__global__ void __launch_bounds__(672)
viterbi_kernel(const float* __restrict__ trans, float* __restrict__ out)
{
    extern __shared__ unsigned char smraw[];
    float* strans = (float*)smraw;                       // 81*81
    float* fvb    = strans + NTAGS * NTAGS;              // 2*81 (double buffer)
    unsigned char* bp = (unsigned char*)(fvb + 2 * NTAGS); // 2048*81
    __shared__ int sbest;

    const int tid = threadIdx.x;
    for (int i = tid; i < NTAGS * NTAGS; i += 672) strans[i] = trans[i];
    if (tid < NTAGS) fvb[tid] = (tid == 79) ? 0.0f : NEGV;   // START=79
    __syncthreads();

    const int i  = tid >> 3;      // target tag
    const int li = tid & 7;       // lane within tag group

    // cache this thread's slice of the transition row in registers
    float trreg[11];
    #pragma unroll
    for (int m = 0; m < 11; m++) {
        int j = li + 8 * m;
        trreg[m] = (i < NTAGS && j < NTAGS) ? strans[i * NTAGS + j] : 0.f;
    }

    for (int t = 0; t < SEQ; t++) {
        const float* fvc = fvb + (t & 1) * NTAGS;
        float*       fvn = fvb + ((t + 1) & 1) * NTAGS;

        float ft = (i < NTAGS && li == 0) ? __ldg(&g_feats[t * NTAGS + i]) : 0.f;

        float best = -3.4e38f; int bj = 0;
        if (i < NTAGS) {
            #pragma unroll
            for (int m = 0; m < 11; m++) {
                int j = li + 8 * m;
                if (j < NTAGS) {
                    float v = fvc[j] + trreg[m];
                    if (v > best) { best = v; bj = j; }
                }
            }
        }
        #pragma unroll
        for (int off = 4; off; off >>= 1) {
            float v2 = __shfl_xor_sync(0xffffffffu, best, off);
            int   j2 = __shfl_xor_sync(0xffffffffu, bj, off);
            if (v2 > best || (v2 == best && j2 < bj)) { best = v2; bj = j2; }
        }
        if (i < NTAGS && li == 0) {
            float nv = best + ft;
            fvn[i] = nv;
            bp[t * NTAGS + i] = (unsigned char)bj;
            g_fv2[t * NTAGS + i] = nv;
        }
        __syncthreads();
    }

    if (tid == 0) {
        const float* fvl  = fvb;                     // (SEQ&1)==0 buffer
        const float* trow = strans + 80 * NTAGS;     // transitions[STOP=80]
        float bv = -3.4e38f; int bi = 0;
        for (int j = 0; j < NTAGS; j++) {
            float v = fvl[j] + trow[j];
            if (v > bv) { bv = v; bi = j; }
        }
        out[0] = bv;                                 // path_score
        sbest  = bi;
        int cur = bi;
        out[1 + SEQ - 1] = (float)cur;               // best_path[T-1]
        for (int t = SEQ - 1; t >= 1; --t) {
            cur = bp[t * NTAGS + cur];
            out[t] = (float)cur;                     // best_path[t-1]
        }
    }
    __syncthreads();
    const int b = sbest;
    for (int k = tid; k < SEQ; k += 672)             // best_tag_score[k] = fv2[T-1-k][best]
        out[1 + SEQ + k] = g_fv2[(SEQ - 1 - k) * NTAGS + b];
}

// ---------------------------------------------------------------------------
// Launch
// ---------------------------------------------------------------------------
extern "C" void kernel_launch(void* const* d_in, const int* in_sizes, int n_in,
                              void* d_out, int out_size)
{
    (void)in_sizes; (void)n_in; (void)out_size;
    const int*   sent  = (const int*)  d_in[0];
    const float* h0    = (const float*)d_in[1];
    const float* c0    = (const float*)d_in[2];
    const float* emb   = (const float*)d_in[3];
    const float* Wih_f = (const float*)d_in[4];
    const float* Whh_f = (const float*)d_in[5];
    const float* bih_f = (const float*)d_in[6];
    const float* bhh_f = (const float*)d_in[7];
    const float* Wih_b = (const float*)d_in[8];
    const float* Whh_b = (const float*)d_in[9];
    const float* bih_b = (const float*)d_in[10];
    const float* bhh_b = (const float*)d_in[11];
    const float* Wt    = (const float*)d_in[12];
    const float* bt    = (const float*)d_in[13];
    const float* trans = (const float*)d_in[14];
    float* out = (float*)d_out;

    init_kernel<<<1, 32>>>();

    dim3 g(G4H / 64, SEQ / 64, 2);
    inproj_kernel<<<g, 256>>>(sent, emb, Wih_f, Wih_b, bih_f, bhh_f, bih_b, bhh_b);

    lstm_kernel<<<128, 256>>>(h0, c0, Whh_f, Whh_b);

    feats_kernel<<<SEQ, 128>>>(Wt, bt);

    cudaFuncSetAttribute(viterbi_kernel,
                         cudaFuncAttributeMaxDynamicSharedMemorySize, VIT_SMEM);
    viterbi_kernel<<<1, 672, VIT_SMEM>>>(trans, out);
}